// round 2
// baseline (speedup 1.0000x reference)
#include <cuda_runtime.h>
#include <cuda_bf16.h>
#include <math.h>

// ----------------------------------------------------------------------------
// DecoderBlock: pre-LN transformer block, B=1, T=4096, C=768, H=12, D=64, F=3072
// Round 1: correct fp32 baseline. SGEMM 128x128x8 w/ 8x8 reg tiles; flash-style
// causal attention (1 query row / thread, online softmax); fused epilogues
// (bias, exact GELU, residual).
// ----------------------------------------------------------------------------

#define T_SEQ 4096
#define C_EMB 768
#define N_HEAD 12
#define D_HEAD 64
#define F_FFN 3072

// scratch (static device globals; no allocations allowed)
__device__ float g_h  [T_SEQ * C_EMB];   // LN1(x)
__device__ float g_q  [T_SEQ * C_EMB];
__device__ float g_k  [T_SEQ * C_EMB];
__device__ float g_v  [T_SEQ * C_EMB];
__device__ float g_ctx[T_SEQ * C_EMB];
__device__ float g_x2 [T_SEQ * C_EMB];   // attn out + residual(h)
__device__ float g_h2 [T_SEQ * C_EMB];   // LN2(x2)
__device__ float g_m1 [T_SEQ * F_FFN];   // gelu(h2@W1+b1)

// ----------------------------------------------------------------------------
// LayerNorm: one block per row (768 cols), 256 threads
// ----------------------------------------------------------------------------
__global__ __launch_bounds__(256) void layernorm_k(
    const float* __restrict__ in, const float* __restrict__ gamma,
    const float* __restrict__ beta, float* __restrict__ out)
{
    int row = blockIdx.x;
    const float* xr = in + (size_t)row * C_EMB;
    float s = 0.f, s2 = 0.f;
    float v0[3];
#pragma unroll
    for (int i = 0; i < 3; i++) {
        float v = xr[threadIdx.x + i * 256];
        v0[i] = v;
        s += v; s2 += v * v;
    }
    // warp reduce
#pragma unroll
    for (int off = 16; off > 0; off >>= 1) {
        s  += __shfl_down_sync(0xffffffffu, s,  off);
        s2 += __shfl_down_sync(0xffffffffu, s2, off);
    }
    __shared__ float shs[8], shs2[8];
    int lane = threadIdx.x & 31, warp = threadIdx.x >> 5;
    if (lane == 0) { shs[warp] = s; shs2[warp] = s2; }
    __syncthreads();
    s = 0.f; s2 = 0.f;
#pragma unroll
    for (int i = 0; i < 8; i++) { s += shs[i]; s2 += shs2[i]; }
    float mu  = s * (1.0f / C_EMB);
    float var = s2 * (1.0f / C_EMB) - mu * mu;
    float inv = rsqrtf(var + 1e-5f);
    float* orow = out + (size_t)row * C_EMB;
#pragma unroll
    for (int i = 0; i < 3; i++) {
        int c = threadIdx.x + i * 256;
        orow[c] = (v0[i] - mu) * inv * gamma[c] + beta[c];
    }
}

// ----------------------------------------------------------------------------
// SGEMM: C[M,N] = A[M,K] @ B[K,N] + bias[N] (+ residual[M,N]) (+ GELU)
// BM=BN=128, BK=8, 256 threads, 8x8 per-thread tiles
// ----------------------------------------------------------------------------
__device__ __forceinline__ float gelu_exact(float v) {
    return 0.5f * v * (1.0f + erff(v * 0.70710678118654752440f));
}

template<int ACT>  // 0 = none, 1 = gelu
__global__ __launch_bounds__(256) void sgemm_k(
    const float* __restrict__ A, const float* __restrict__ B,
    const float* __restrict__ bias, const float* __restrict__ res,
    float* __restrict__ C, int M, int N, int K)
{
    constexpr int BM = 128, BN = 128, BK = 8;
    __shared__ float As[BK][BM];
    __shared__ float Bs[BK][BN];

    int tid = threadIdx.x;
    int bm = blockIdx.y * BM;
    int bn = blockIdx.x * BN;
    int tx = tid & 15;        // 0..15 -> 128 cols / 8
    int ty = tid >> 4;        // 0..15 -> 128 rows / 8

    // A loads: 128 rows x 8 cols = 256 float4; thread -> row tid/2, col4 (tid%2)*4
    int a_r = tid >> 1, a_c = (tid & 1) * 4;
    // B loads: 8 rows x 128 cols = 256 float4; thread -> row tid/32, col (tid%32)*4
    int b_r = tid >> 5, b_c = (tid & 31) * 4;

    const float* Aptr = A + (size_t)(bm + a_r) * K + a_c;
    const float* Bptr = B + (size_t)b_r * N + bn + b_c;

    float acc[8][8];
#pragma unroll
    for (int i = 0; i < 8; i++)
#pragma unroll
        for (int j = 0; j < 8; j++) acc[i][j] = 0.f;

    for (int k0 = 0; k0 < K; k0 += BK) {
        float4 av = *(const float4*)(Aptr + k0);
        float4 bv = *(const float4*)(Bptr + (size_t)k0 * N);
        As[a_c + 0][a_r] = av.x;
        As[a_c + 1][a_r] = av.y;
        As[a_c + 2][a_r] = av.z;
        As[a_c + 3][a_r] = av.w;
        *(float4*)&Bs[b_r][b_c] = bv;
        __syncthreads();
#pragma unroll
        for (int k = 0; k < BK; k++) {
            float4 a0 = *(const float4*)&As[k][ty * 8];
            float4 a1 = *(const float4*)&As[k][ty * 8 + 4];
            float4 b0 = *(const float4*)&Bs[k][tx * 8];
            float4 b1 = *(const float4*)&Bs[k][tx * 8 + 4];
            float ar[8] = {a0.x, a0.y, a0.z, a0.w, a1.x, a1.y, a1.z, a1.w};
            float br[8] = {b0.x, b0.y, b0.z, b0.w, b1.x, b1.y, b1.z, b1.w};
#pragma unroll
            for (int i = 0; i < 8; i++)
#pragma unroll
                for (int j = 0; j < 8; j++)
                    acc[i][j] = fmaf(ar[i], br[j], acc[i][j]);
        }
        __syncthreads();
    }

#pragma unroll
    for (int i = 0; i < 8; i++) {
        int row = bm + ty * 8 + i;
#pragma unroll
        for (int j = 0; j < 8; j++) {
            int col = bn + tx * 8 + j;
            float v = acc[i][j] + bias[col];
            if (res) v += res[(size_t)row * N + col];
            if (ACT == 1) v = gelu_exact(v);
            C[(size_t)row * N + col] = v;
        }
    }
}

// ----------------------------------------------------------------------------
// Causal attention, flash-style: grid (T/128, H), 128 threads; each thread owns
// one query row (q + o accumulator in registers), K/V tiles of 64 keys in SMEM,
// online softmax.
// ----------------------------------------------------------------------------
__global__ __launch_bounds__(128) void attn_k(
    const float* __restrict__ Q, const float* __restrict__ K,
    const float* __restrict__ V, float* __restrict__ O)
{
    int hd = blockIdx.y;
    int r = blockIdx.x * 128 + threadIdx.x;

    __shared__ float Ks[64][64];
    __shared__ float Vs[64][64];

    float qv[64];
    const float* qp = Q + (size_t)r * C_EMB + hd * D_HEAD;
#pragma unroll
    for (int d4 = 0; d4 < 16; d4++) {
        float4 t = *(const float4*)(qp + d4 * 4);
        qv[d4 * 4 + 0] = t.x; qv[d4 * 4 + 1] = t.y;
        qv[d4 * 4 + 2] = t.z; qv[d4 * 4 + 3] = t.w;
    }
    float o[64];
#pragma unroll
    for (int d = 0; d < 64; d++) o[d] = 0.f;
    float m = -INFINITY, l = 0.f;

    int kb_last = (blockIdx.x * 128 + 127) >> 6;   // inclusive
    for (int kb = 0; kb <= kb_last; kb++) {
        // cooperative K/V tile load: 64x64 floats each
#pragma unroll
        for (int l4 = 0; l4 < 8; l4++) {
            int idx = l4 * 128 + threadIdx.x;      // 0..1023 float4 slots
            int rr = idx >> 4, c4 = (idx & 15) * 4;
            size_t goff = (size_t)(kb * 64 + rr) * C_EMB + hd * D_HEAD + c4;
            *(float4*)&Ks[rr][c4] = *(const float4*)(K + goff);
            *(float4*)&Vs[rr][c4] = *(const float4*)(V + goff);
        }
        __syncthreads();

        int jmax = r - kb * 64;                    // inclusive local key limit
        if (jmax > 63) jmax = 63;
        for (int j = 0; j <= jmax; j++) {
            float s = 0.f;
            const float4* kr = (const float4*)Ks[j];
#pragma unroll
            for (int d4 = 0; d4 < 16; d4++) {
                float4 kv = kr[d4];
                s = fmaf(qv[d4 * 4 + 0], kv.x, s);
                s = fmaf(qv[d4 * 4 + 1], kv.y, s);
                s = fmaf(qv[d4 * 4 + 2], kv.z, s);
                s = fmaf(qv[d4 * 4 + 3], kv.w, s);
            }
            s *= 0.125f;   // 1/sqrt(64)
            if (s > m) {
                float c = __expf(m - s);
#pragma unroll
                for (int d = 0; d < 64; d++) o[d] *= c;
                l *= c;
                m = s;
            }
            float p = __expf(s - m);
            l += p;
            const float4* vr = (const float4*)Vs[j];
#pragma unroll
            for (int d4 = 0; d4 < 16; d4++) {
                float4 vv = vr[d4];
                o[d4 * 4 + 0] = fmaf(p, vv.x, o[d4 * 4 + 0]);
                o[d4 * 4 + 1] = fmaf(p, vv.y, o[d4 * 4 + 1]);
                o[d4 * 4 + 2] = fmaf(p, vv.z, o[d4 * 4 + 2]);
                o[d4 * 4 + 3] = fmaf(p, vv.w, o[d4 * 4 + 3]);
            }
        }
        __syncthreads();
    }

    float inv = 1.0f / l;
    float* op = O + (size_t)r * C_EMB + hd * D_HEAD;
#pragma unroll
    for (int d4 = 0; d4 < 16; d4++) {
        float4 t;
        t.x = o[d4 * 4 + 0] * inv; t.y = o[d4 * 4 + 1] * inv;
        t.z = o[d4 * 4 + 2] * inv; t.w = o[d4 * 4 + 3] * inv;
        *(float4*)(op + d4 * 4) = t;
    }
}

// ----------------------------------------------------------------------------
// launch
// ----------------------------------------------------------------------------
extern "C" void kernel_launch(void* const* d_in, const int* in_sizes, int n_in,
                              void* d_out, int out_size)
{
    const float* x     = (const float*)d_in[0];
    const float* Wq    = (const float*)d_in[1];
    const float* bq    = (const float*)d_in[2];
    const float* Wk    = (const float*)d_in[3];
    const float* bk    = (const float*)d_in[4];
    const float* Wv    = (const float*)d_in[5];
    const float* bv    = (const float*)d_in[6];
    const float* Wo    = (const float*)d_in[7];
    const float* bo    = (const float*)d_in[8];
    const float* ln1_g = (const float*)d_in[9];
    const float* ln1_b = (const float*)d_in[10];
    const float* ln2_g = (const float*)d_in[11];
    const float* ln2_b = (const float*)d_in[12];
    const float* W1    = (const float*)d_in[13];
    const float* b1    = (const float*)d_in[14];
    const float* W2    = (const float*)d_in[15];
    const float* b2    = (const float*)d_in[16];
    float* out = (float*)d_out;

    float *h, *q, *k, *v, *ctx, *x2, *h2, *m1;
    cudaGetSymbolAddress((void**)&h,   g_h);
    cudaGetSymbolAddress((void**)&q,   g_q);
    cudaGetSymbolAddress((void**)&k,   g_k);
    cudaGetSymbolAddress((void**)&v,   g_v);
    cudaGetSymbolAddress((void**)&ctx, g_ctx);
    cudaGetSymbolAddress((void**)&x2,  g_x2);
    cudaGetSymbolAddress((void**)&h2,  g_h2);
    cudaGetSymbolAddress((void**)&m1,  g_m1);

    dim3 gC(C_EMB / 128, T_SEQ / 128);   // (6, 32)
    dim3 gF(F_FFN / 128, T_SEQ / 128);   // (24, 32)

    // 1. h = LN1(x)
    layernorm_k<<<T_SEQ, 256>>>(x, ln1_g, ln1_b, h);
    // 2. q,k,v = h @ W{q,k,v} + b
    sgemm_k<0><<<gC, 256>>>(h, Wq, bq, nullptr, q, T_SEQ, C_EMB, C_EMB);
    sgemm_k<0><<<gC, 256>>>(h, Wk, bk, nullptr, k, T_SEQ, C_EMB, C_EMB);
    sgemm_k<0><<<gC, 256>>>(h, Wv, bv, nullptr, v, T_SEQ, C_EMB, C_EMB);
    // 3. causal attention -> ctx
    attn_k<<<dim3(T_SEQ / 128, N_HEAD), 128>>>(q, k, v, ctx);
    // 4. x2 = ctx @ Wo + bo + h
    sgemm_k<0><<<gC, 256>>>(ctx, Wo, bo, h, x2, T_SEQ, C_EMB, C_EMB);
    // 5. h2 = LN2(x2)
    layernorm_k<<<T_SEQ, 256>>>(x2, ln2_g, ln2_b, h2);
    // 6. m1 = gelu(h2 @ W1 + b1)
    sgemm_k<1><<<gF, 256>>>(h2, W1, b1, nullptr, m1, T_SEQ, F_FFN, C_EMB);
    // 7. out = m1 @ W2 + b2 + h2
    sgemm_k<0><<<gC, 256>>>(m1, W2, b2, h2, out, T_SEQ, C_EMB, F_FFN);
}

// round 3
// speedup vs baseline: 1.4992x; 1.4992x over previous
#include <cuda_runtime.h>
#include <cuda_bf16.h>
#include <math.h>
#include <stdint.h>

// ----------------------------------------------------------------------------
// DecoderBlock: B=1, T=4096, C=768, H=12, D=64, F=3072
// Round 3: all GEMMs on tensor cores via mma.sync m16n8k8 tf32 (fp32 accum),
// double-buffered 128x128x16 tiles, fused epilogues. Attention/LN unchanged.
// ----------------------------------------------------------------------------

#define T_SEQ 4096
#define C_EMB 768
#define N_HEAD 12
#define D_HEAD 64
#define F_FFN 3072

__device__ float g_h  [T_SEQ * C_EMB];
__device__ float g_q  [T_SEQ * C_EMB];
__device__ float g_k  [T_SEQ * C_EMB];
__device__ float g_v  [T_SEQ * C_EMB];
__device__ float g_ctx[T_SEQ * C_EMB];
__device__ float g_x2 [T_SEQ * C_EMB];
__device__ float g_h2 [T_SEQ * C_EMB];
__device__ float g_m1 [T_SEQ * F_FFN];

// ----------------------------------------------------------------------------
// LayerNorm (unchanged)
// ----------------------------------------------------------------------------
__global__ __launch_bounds__(256) void layernorm_k(
    const float* __restrict__ in, const float* __restrict__ gamma,
    const float* __restrict__ beta, float* __restrict__ out)
{
    int row = blockIdx.x;
    const float* xr = in + (size_t)row * C_EMB;
    float s = 0.f, s2 = 0.f;
    float v0[3];
#pragma unroll
    for (int i = 0; i < 3; i++) {
        float v = xr[threadIdx.x + i * 256];
        v0[i] = v;
        s += v; s2 += v * v;
    }
#pragma unroll
    for (int off = 16; off > 0; off >>= 1) {
        s  += __shfl_down_sync(0xffffffffu, s,  off);
        s2 += __shfl_down_sync(0xffffffffu, s2, off);
    }
    __shared__ float shs[8], shs2[8];
    int lane = threadIdx.x & 31, warp = threadIdx.x >> 5;
    if (lane == 0) { shs[warp] = s; shs2[warp] = s2; }
    __syncthreads();
    s = 0.f; s2 = 0.f;
#pragma unroll
    for (int i = 0; i < 8; i++) { s += shs[i]; s2 += shs2[i]; }
    float mu  = s * (1.0f / C_EMB);
    float var = s2 * (1.0f / C_EMB) - mu * mu;
    float inv = rsqrtf(var + 1e-5f);
    float* orow = out + (size_t)row * C_EMB;
#pragma unroll
    for (int i = 0; i < 3; i++) {
        int c = threadIdx.x + i * 256;
        orow[c] = (v0[i] - mu) * inv * gamma[c] + beta[c];
    }
}

// ----------------------------------------------------------------------------
// tf32 mma.sync GEMM: C[M,N] = A[M,K] @ B[K,N] + bias (+res) (+GELU)
// BM=BN=128, BK=16, 256 threads (8 warps, 2x4), warp tile 64x32,
// mma m16n8k8: 4x4 tiles/warp/k-step, 2 k-steps per BK.
// ----------------------------------------------------------------------------
__device__ __forceinline__ uint32_t f2tf32(float f) {
    uint32_t r;
    asm("cvt.rna.tf32.f32 %0, %1;" : "=r"(r) : "f"(f));
    return r;
}

__device__ __forceinline__ void mma_tf32(float* d, const uint32_t* a, const uint32_t* b) {
    asm volatile(
        "mma.sync.aligned.m16n8k8.row.col.f32.tf32.tf32.f32 "
        "{%0,%1,%2,%3}, {%4,%5,%6,%7}, {%8,%9}, {%0,%1,%2,%3};\n"
        : "+f"(d[0]), "+f"(d[1]), "+f"(d[2]), "+f"(d[3])
        : "r"(a[0]), "r"(a[1]), "r"(a[2]), "r"(a[3]), "r"(b[0]), "r"(b[1]));
}

__device__ __forceinline__ float gelu_exact(float v) {
    return 0.5f * v * (1.0f + erff(v * 0.70710678118654752440f));
}

template<int ACT>
__global__ __launch_bounds__(256) void mmgemm_k(
    const float* __restrict__ A, const float* __restrict__ B,
    const float* __restrict__ bias, const float* __restrict__ res,
    float* __restrict__ C, int M, int N, int K)
{
    constexpr int BM = 128, BN = 128, BK = 16;
    constexpr int AS = BK + 4;    // 20: bank-conflict-free fragment reads
    constexpr int BS = BN + 8;    // 136: bank-conflict-free fragment reads
    __shared__ uint32_t As[2][BM][AS];
    __shared__ uint32_t Bs[2][BK][BS];

    int tid  = threadIdx.x;
    int lane = tid & 31;
    int wid  = tid >> 5;
    int wm   = wid & 1;          // 0..1 -> 64 rows each
    int wn   = wid >> 1;         // 0..3 -> 32 cols each
    int gid  = lane >> 2;        // 0..7
    int tig  = lane & 3;         // 0..3

    int bm = blockIdx.y * BM;
    int bn = blockIdx.x * BN;

    // global-load mapping
    int a_r  = tid >> 2;         // 0..63? no: 256 threads, id covers 512 f4 in 2 iters
    int a_c4 = tid & 3;
    int b_r  = tid >> 5;
    int b_c4 = tid & 31;

    float acc[4][4][4];
#pragma unroll
    for (int i = 0; i < 4; i++)
#pragma unroll
        for (int j = 0; j < 4; j++)
#pragma unroll
            for (int r = 0; r < 4; r++) acc[i][j][r] = 0.f;

    int nt = K / BK;

    // helper lambdas inlined manually: load stage `kt` global -> regs
    float4 av[2], bv[2];
    {
        // stage 0
#pragma unroll
        for (int i = 0; i < 2; i++) {
            int id = tid + i * 256;
            int r = id >> 2, c4 = id & 3;
            av[i] = *(const float4*)(A + (size_t)(bm + r) * K + c4 * 4);
            int rb = id >> 5, cb = id & 31;
            bv[i] = *(const float4*)(B + (size_t)rb * N + bn + cb * 4);
        }
#pragma unroll
        for (int i = 0; i < 2; i++) {
            int id = tid + i * 256;
            int r = id >> 2, c4 = id & 3;
            As[0][r][c4 * 4 + 0] = f2tf32(av[i].x);
            As[0][r][c4 * 4 + 1] = f2tf32(av[i].y);
            As[0][r][c4 * 4 + 2] = f2tf32(av[i].z);
            As[0][r][c4 * 4 + 3] = f2tf32(av[i].w);
            int rb = id >> 5, cb = id & 31;
            Bs[0][rb][cb * 4 + 0] = f2tf32(bv[i].x);
            Bs[0][rb][cb * 4 + 1] = f2tf32(bv[i].y);
            Bs[0][rb][cb * 4 + 2] = f2tf32(bv[i].z);
            Bs[0][rb][cb * 4 + 3] = f2tf32(bv[i].w);
        }
    }
    __syncthreads();

    for (int kt = 0; kt < nt; kt++) {
        int buf = kt & 1, nxt = buf ^ 1;
        bool has_next = (kt + 1 < nt);
        if (has_next) {
            int k0 = (kt + 1) * BK;
#pragma unroll
            for (int i = 0; i < 2; i++) {
                int id = tid + i * 256;
                int r = id >> 2, c4 = id & 3;
                av[i] = *(const float4*)(A + (size_t)(bm + r) * K + k0 + c4 * 4);
                int rb = id >> 5, cb = id & 31;
                bv[i] = *(const float4*)(B + (size_t)(k0 + rb) * N + bn + cb * 4);
            }
        }

        // compute 2 k-steps of 8
#pragma unroll
        for (int ks = 0; ks < 2; ks++) {
            uint32_t afr[4][4];
            uint32_t bfr[4][2];
            int kk = ks * 8;
#pragma unroll
            for (int mt = 0; mt < 4; mt++) {
                int r0 = wm * 64 + mt * 16 + gid;
                afr[mt][0] = As[buf][r0    ][kk + tig];
                afr[mt][1] = As[buf][r0 + 8][kk + tig];
                afr[mt][2] = As[buf][r0    ][kk + tig + 4];
                afr[mt][3] = As[buf][r0 + 8][kk + tig + 4];
            }
#pragma unroll
            for (int ntl = 0; ntl < 4; ntl++) {
                int c0 = wn * 32 + ntl * 8 + gid;
                bfr[ntl][0] = Bs[buf][kk + tig    ][c0];
                bfr[ntl][1] = Bs[buf][kk + tig + 4][c0];
            }
#pragma unroll
            for (int mt = 0; mt < 4; mt++)
#pragma unroll
                for (int ntl = 0; ntl < 4; ntl++)
                    mma_tf32(acc[mt][ntl], afr[mt], bfr[ntl]);
        }

        if (has_next) {
#pragma unroll
            for (int i = 0; i < 2; i++) {
                int id = tid + i * 256;
                int r = id >> 2, c4 = id & 3;
                As[nxt][r][c4 * 4 + 0] = f2tf32(av[i].x);
                As[nxt][r][c4 * 4 + 1] = f2tf32(av[i].y);
                As[nxt][r][c4 * 4 + 2] = f2tf32(av[i].z);
                As[nxt][r][c4 * 4 + 3] = f2tf32(av[i].w);
                int rb = id >> 5, cb = id & 31;
                Bs[nxt][rb][cb * 4 + 0] = f2tf32(bv[i].x);
                Bs[nxt][rb][cb * 4 + 1] = f2tf32(bv[i].y);
                Bs[nxt][rb][cb * 4 + 2] = f2tf32(bv[i].z);
                Bs[nxt][rb][cb * 4 + 3] = f2tf32(bv[i].w);
            }
            __syncthreads();
        }
    }

    // epilogue
#pragma unroll
    for (int mt = 0; mt < 4; mt++) {
#pragma unroll
        for (int ntl = 0; ntl < 4; ntl++) {
#pragma unroll
            for (int r = 0; r < 4; r++) {
                int row = bm + wm * 64 + mt * 16 + gid + (r >> 1) * 8;
                int col = bn + wn * 32 + ntl * 8 + tig * 2 + (r & 1);
                float v = acc[mt][ntl][r] + bias[col];
                if (res) v += res[(size_t)row * N + col];
                if (ACT == 1) v = gelu_exact(v);
                C[(size_t)row * N + col] = v;
            }
        }
    }
}

// ----------------------------------------------------------------------------
// Causal attention (unchanged from R1)
// ----------------------------------------------------------------------------
__global__ __launch_bounds__(128) void attn_k(
    const float* __restrict__ Q, const float* __restrict__ K,
    const float* __restrict__ V, float* __restrict__ O)
{
    int hd = blockIdx.y;
    int r = blockIdx.x * 128 + threadIdx.x;

    __shared__ float Ks[64][64];
    __shared__ float Vs[64][64];

    float qv[64];
    const float* qp = Q + (size_t)r * C_EMB + hd * D_HEAD;
#pragma unroll
    for (int d4 = 0; d4 < 16; d4++) {
        float4 t = *(const float4*)(qp + d4 * 4);
        qv[d4 * 4 + 0] = t.x; qv[d4 * 4 + 1] = t.y;
        qv[d4 * 4 + 2] = t.z; qv[d4 * 4 + 3] = t.w;
    }
    float o[64];
#pragma unroll
    for (int d = 0; d < 64; d++) o[d] = 0.f;
    float m = -INFINITY, l = 0.f;

    int kb_last = (blockIdx.x * 128 + 127) >> 6;
    for (int kb = 0; kb <= kb_last; kb++) {
#pragma unroll
        for (int l4 = 0; l4 < 8; l4++) {
            int idx = l4 * 128 + threadIdx.x;
            int rr = idx >> 4, c4 = (idx & 15) * 4;
            size_t goff = (size_t)(kb * 64 + rr) * C_EMB + hd * D_HEAD + c4;
            *(float4*)&Ks[rr][c4] = *(const float4*)(K + goff);
            *(float4*)&Vs[rr][c4] = *(const float4*)(V + goff);
        }
        __syncthreads();

        int jmax = r - kb * 64;
        if (jmax > 63) jmax = 63;
        for (int j = 0; j <= jmax; j++) {
            float s = 0.f;
            const float4* kr = (const float4*)Ks[j];
#pragma unroll
            for (int d4 = 0; d4 < 16; d4++) {
                float4 kv = kr[d4];
                s = fmaf(qv[d4 * 4 + 0], kv.x, s);
                s = fmaf(qv[d4 * 4 + 1], kv.y, s);
                s = fmaf(qv[d4 * 4 + 2], kv.z, s);
                s = fmaf(qv[d4 * 4 + 3], kv.w, s);
            }
            s *= 0.125f;
            if (s > m) {
                float c = __expf(m - s);
#pragma unroll
                for (int d = 0; d < 64; d++) o[d] *= c;
                l *= c;
                m = s;
            }
            float p = __expf(s - m);
            l += p;
            const float4* vr = (const float4*)Vs[j];
#pragma unroll
            for (int d4 = 0; d4 < 16; d4++) {
                float4 vv = vr[d4];
                o[d4 * 4 + 0] = fmaf(p, vv.x, o[d4 * 4 + 0]);
                o[d4 * 4 + 1] = fmaf(p, vv.y, o[d4 * 4 + 1]);
                o[d4 * 4 + 2] = fmaf(p, vv.z, o[d4 * 4 + 2]);
                o[d4 * 4 + 3] = fmaf(p, vv.w, o[d4 * 4 + 3]);
            }
        }
        __syncthreads();
    }

    float inv = 1.0f / l;
    float* op = O + (size_t)r * C_EMB + hd * D_HEAD;
#pragma unroll
    for (int d4 = 0; d4 < 16; d4++) {
        float4 t;
        t.x = o[d4 * 4 + 0] * inv; t.y = o[d4 * 4 + 1] * inv;
        t.z = o[d4 * 4 + 2] * inv; t.w = o[d4 * 4 + 3] * inv;
        *(float4*)(op + d4 * 4) = t;
    }
}

// ----------------------------------------------------------------------------
// launch
// ----------------------------------------------------------------------------
extern "C" void kernel_launch(void* const* d_in, const int* in_sizes, int n_in,
                              void* d_out, int out_size)
{
    const float* x     = (const float*)d_in[0];
    const float* Wq    = (const float*)d_in[1];
    const float* bq    = (const float*)d_in[2];
    const float* Wk    = (const float*)d_in[3];
    const float* bk    = (const float*)d_in[4];
    const float* Wv    = (const float*)d_in[5];
    const float* bv    = (const float*)d_in[6];
    const float* Wo    = (const float*)d_in[7];
    const float* bo    = (const float*)d_in[8];
    const float* ln1_g = (const float*)d_in[9];
    const float* ln1_b = (const float*)d_in[10];
    const float* ln2_g = (const float*)d_in[11];
    const float* ln2_b = (const float*)d_in[12];
    const float* W1    = (const float*)d_in[13];
    const float* b1    = (const float*)d_in[14];
    const float* W2    = (const float*)d_in[15];
    const float* b2    = (const float*)d_in[16];
    float* out = (float*)d_out;

    float *h, *q, *k, *v, *ctx, *x2, *h2, *m1;
    cudaGetSymbolAddress((void**)&h,   g_h);
    cudaGetSymbolAddress((void**)&q,   g_q);
    cudaGetSymbolAddress((void**)&k,   g_k);
    cudaGetSymbolAddress((void**)&v,   g_v);
    cudaGetSymbolAddress((void**)&ctx, g_ctx);
    cudaGetSymbolAddress((void**)&x2,  g_x2);
    cudaGetSymbolAddress((void**)&h2,  g_h2);
    cudaGetSymbolAddress((void**)&m1,  g_m1);

    dim3 gC(C_EMB / 128, T_SEQ / 128);   // (6, 32)
    dim3 gF(F_FFN / 128, T_SEQ / 128);   // (24, 32)

    layernorm_k<<<T_SEQ, 256>>>(x, ln1_g, ln1_b, h);
    mmgemm_k<0><<<gC, 256>>>(h, Wq, bq, nullptr, q, T_SEQ, C_EMB, C_EMB);
    mmgemm_k<0><<<gC, 256>>>(h, Wk, bk, nullptr, k, T_SEQ, C_EMB, C_EMB);
    mmgemm_k<0><<<gC, 256>>>(h, Wv, bv, nullptr, v, T_SEQ, C_EMB, C_EMB);
    attn_k<<<dim3(T_SEQ / 128, N_HEAD), 128>>>(q, k, v, ctx);
    mmgemm_k<0><<<gC, 256>>>(ctx, Wo, bo, h, x2, T_SEQ, C_EMB, C_EMB);
    layernorm_k<<<T_SEQ, 256>>>(x2, ln2_g, ln2_b, h2);
    mmgemm_k<1><<<gF, 256>>>(h2, W1, b1, nullptr, m1, T_SEQ, F_FFN, C_EMB);
    mmgemm_k<0><<<gC, 256>>>(m1, W2, b2, h2, out, T_SEQ, C_EMB, F_FFN);
}

// round 6
// speedup vs baseline: 3.3545x; 2.2375x over previous
#include <cuda_runtime.h>
#include <cuda_bf16.h>
#include <math.h>
#include <stdint.h>

// ----------------------------------------------------------------------------
// DecoderBlock: B=1, T=4096, C=768, H=12, D=64, F=3072
// Round 6: tf32 tensor-core flash attention with FIXED causal boundary gate
// (R4/R5 masked per warp-max row; tiles ending inside the warp's 16-row span
// were left unmasked -> future-key leakage on 1/4 of rows = the 1.3e-3 error).
// Plain tf32 (fast path); normalization uses quantized p. GEMMs/LN from R3.
// ----------------------------------------------------------------------------

#define T_SEQ 4096
#define C_EMB 768
#define N_HEAD 12
#define D_HEAD 64
#define F_FFN 3072

__device__ float g_h  [T_SEQ * C_EMB];
__device__ float g_q  [T_SEQ * C_EMB];
__device__ float g_k  [T_SEQ * C_EMB];
__device__ float g_v  [T_SEQ * C_EMB];
__device__ float g_ctx[T_SEQ * C_EMB];
__device__ float g_x2 [T_SEQ * C_EMB];
__device__ float g_h2 [T_SEQ * C_EMB];
__device__ float g_m1 [T_SEQ * F_FFN];

// ----------------------------------------------------------------------------
// LayerNorm (unchanged)
// ----------------------------------------------------------------------------
__global__ __launch_bounds__(256) void layernorm_k(
    const float* __restrict__ in, const float* __restrict__ gamma,
    const float* __restrict__ beta, float* __restrict__ out)
{
    int row = blockIdx.x;
    const float* xr = in + (size_t)row * C_EMB;
    float s = 0.f, s2 = 0.f;
    float v0[3];
#pragma unroll
    for (int i = 0; i < 3; i++) {
        float v = xr[threadIdx.x + i * 256];
        v0[i] = v;
        s += v; s2 += v * v;
    }
#pragma unroll
    for (int off = 16; off > 0; off >>= 1) {
        s  += __shfl_down_sync(0xffffffffu, s,  off);
        s2 += __shfl_down_sync(0xffffffffu, s2, off);
    }
    __shared__ float shs[8], shs2[8];
    int lane = threadIdx.x & 31, warp = threadIdx.x >> 5;
    if (lane == 0) { shs[warp] = s; shs2[warp] = s2; }
    __syncthreads();
    s = 0.f; s2 = 0.f;
#pragma unroll
    for (int i = 0; i < 8; i++) { s += shs[i]; s2 += shs2[i]; }
    float mu  = s * (1.0f / C_EMB);
    float var = s2 * (1.0f / C_EMB) - mu * mu;
    float inv = rsqrtf(var + 1e-5f);
    float* orow = out + (size_t)row * C_EMB;
#pragma unroll
    for (int i = 0; i < 3; i++) {
        int c = threadIdx.x + i * 256;
        orow[c] = (v0[i] - mu) * inv * gamma[c] + beta[c];
    }
}

// ----------------------------------------------------------------------------
// tf32 helpers
// ----------------------------------------------------------------------------
__device__ __forceinline__ uint32_t f2tf32(float f) {
    uint32_t r;
    asm("cvt.rna.tf32.f32 %0, %1;" : "=r"(r) : "f"(f));
    return r;
}

__device__ __forceinline__ void mma_tf32(float* d, const uint32_t* a, const uint32_t* b) {
    asm volatile(
        "mma.sync.aligned.m16n8k8.row.col.f32.tf32.tf32.f32 "
        "{%0,%1,%2,%3}, {%4,%5,%6,%7}, {%8,%9}, {%0,%1,%2,%3};\n"
        : "+f"(d[0]), "+f"(d[1]), "+f"(d[2]), "+f"(d[3])
        : "r"(a[0]), "r"(a[1]), "r"(a[2]), "r"(a[3]), "r"(b[0]), "r"(b[1]));
}

__device__ __forceinline__ float gelu_exact(float v) {
    return 0.5f * v * (1.0f + erff(v * 0.70710678118654752440f));
}

// ----------------------------------------------------------------------------
// tf32 mma GEMM (unchanged from R3, passing)
// ----------------------------------------------------------------------------
template<int ACT>
__global__ __launch_bounds__(256) void mmgemm_k(
    const float* __restrict__ A, const float* __restrict__ B,
    const float* __restrict__ bias, const float* __restrict__ res,
    float* __restrict__ C, int M, int N, int K)
{
    constexpr int BM = 128, BN = 128, BK = 16;
    constexpr int AS = BK + 4;
    constexpr int BS = BN + 8;
    __shared__ uint32_t As[2][BM][AS];
    __shared__ uint32_t Bs[2][BK][BS];

    int tid  = threadIdx.x;
    int lane = tid & 31;
    int wid  = tid >> 5;
    int wm   = wid & 1;
    int wn   = wid >> 1;
    int gid  = lane >> 2;
    int tig  = lane & 3;

    int bm = blockIdx.y * BM;
    int bn = blockIdx.x * BN;

    float acc[4][4][4];
#pragma unroll
    for (int i = 0; i < 4; i++)
#pragma unroll
        for (int j = 0; j < 4; j++)
#pragma unroll
            for (int r = 0; r < 4; r++) acc[i][j][r] = 0.f;

    int nt = K / BK;

    float4 av[2], bv[2];
    {
#pragma unroll
        for (int i = 0; i < 2; i++) {
            int id = tid + i * 256;
            int r = id >> 2, c4 = id & 3;
            av[i] = *(const float4*)(A + (size_t)(bm + r) * K + c4 * 4);
            int rb = id >> 5, cb = id & 31;
            bv[i] = *(const float4*)(B + (size_t)rb * N + bn + cb * 4);
        }
#pragma unroll
        for (int i = 0; i < 2; i++) {
            int id = tid + i * 256;
            int r = id >> 2, c4 = id & 3;
            As[0][r][c4 * 4 + 0] = f2tf32(av[i].x);
            As[0][r][c4 * 4 + 1] = f2tf32(av[i].y);
            As[0][r][c4 * 4 + 2] = f2tf32(av[i].z);
            As[0][r][c4 * 4 + 3] = f2tf32(av[i].w);
            int rb = id >> 5, cb = id & 31;
            Bs[0][rb][cb * 4 + 0] = f2tf32(bv[i].x);
            Bs[0][rb][cb * 4 + 1] = f2tf32(bv[i].y);
            Bs[0][rb][cb * 4 + 2] = f2tf32(bv[i].z);
            Bs[0][rb][cb * 4 + 3] = f2tf32(bv[i].w);
        }
    }
    __syncthreads();

    for (int kt = 0; kt < nt; kt++) {
        int buf = kt & 1, nxt = buf ^ 1;
        bool has_next = (kt + 1 < nt);
        if (has_next) {
            int k0 = (kt + 1) * BK;
#pragma unroll
            for (int i = 0; i < 2; i++) {
                int id = tid + i * 256;
                int r = id >> 2, c4 = id & 3;
                av[i] = *(const float4*)(A + (size_t)(bm + r) * K + k0 + c4 * 4);
                int rb = id >> 5, cb = id & 31;
                bv[i] = *(const float4*)(B + (size_t)(k0 + rb) * N + bn + cb * 4);
            }
        }

#pragma unroll
        for (int ks = 0; ks < 2; ks++) {
            uint32_t afr[4][4];
            uint32_t bfr[4][2];
            int kk = ks * 8;
#pragma unroll
            for (int mt = 0; mt < 4; mt++) {
                int r0 = wm * 64 + mt * 16 + gid;
                afr[mt][0] = As[buf][r0    ][kk + tig];
                afr[mt][1] = As[buf][r0 + 8][kk + tig];
                afr[mt][2] = As[buf][r0    ][kk + tig + 4];
                afr[mt][3] = As[buf][r0 + 8][kk + tig + 4];
            }
#pragma unroll
            for (int ntl = 0; ntl < 4; ntl++) {
                int c0 = wn * 32 + ntl * 8 + gid;
                bfr[ntl][0] = Bs[buf][kk + tig    ][c0];
                bfr[ntl][1] = Bs[buf][kk + tig + 4][c0];
            }
#pragma unroll
            for (int mt = 0; mt < 4; mt++)
#pragma unroll
                for (int ntl = 0; ntl < 4; ntl++)
                    mma_tf32(acc[mt][ntl], afr[mt], bfr[ntl]);
        }

        if (has_next) {
#pragma unroll
            for (int i = 0; i < 2; i++) {
                int id = tid + i * 256;
                int r = id >> 2, c4 = id & 3;
                As[nxt][r][c4 * 4 + 0] = f2tf32(av[i].x);
                As[nxt][r][c4 * 4 + 1] = f2tf32(av[i].y);
                As[nxt][r][c4 * 4 + 2] = f2tf32(av[i].z);
                As[nxt][r][c4 * 4 + 3] = f2tf32(av[i].w);
                int rb = id >> 5, cb = id & 31;
                Bs[nxt][rb][cb * 4 + 0] = f2tf32(bv[i].x);
                Bs[nxt][rb][cb * 4 + 1] = f2tf32(bv[i].y);
                Bs[nxt][rb][cb * 4 + 2] = f2tf32(bv[i].z);
                Bs[nxt][rb][cb * 4 + 3] = f2tf32(bv[i].w);
            }
            __syncthreads();
        }
    }

#pragma unroll
    for (int mt = 0; mt < 4; mt++) {
#pragma unroll
        for (int ntl = 0; ntl < 4; ntl++) {
#pragma unroll
            for (int r = 0; r < 4; r++) {
                int row = bm + wm * 64 + mt * 16 + gid + (r >> 1) * 8;
                int col = bn + wn * 32 + ntl * 8 + tig * 2 + (r & 1);
                float v = acc[mt][ntl][r] + bias[col];
                if (res) v += res[(size_t)row * N + col];
                if (ACT == 1) v = gelu_exact(v);
                C[(size_t)row * N + col] = v;
            }
        }
    }
}

// ----------------------------------------------------------------------------
// Flash attention, tensor cores (tf32), fixed causal gate.
// Block = (head, 128-q tile), 8 warps; warp owns 16 query rows; key tile = 64.
// ----------------------------------------------------------------------------
#define KS_STRIDE 68
#define VS_STRIDE 72
#define ATTN_SMEM_BYTES ((64 * KS_STRIDE + 64 * VS_STRIDE + 8 * 16 * KS_STRIDE) * 4)

__global__ __launch_bounds__(256, 2) void fattn_k(
    const float* __restrict__ Q, const float* __restrict__ Kg,
    const float* __restrict__ Vg, float* __restrict__ O)
{
    extern __shared__ uint32_t sm[];
    uint32_t* Ks = sm;                         // [64][68]
    uint32_t* Vs = Ks + 64 * KS_STRIDE;        // [64][72]
    uint32_t* Ps = Vs + 64 * VS_STRIDE;        // [8][16][68]

    int hd   = blockIdx.y;
    int qt   = (int)gridDim.x - 1 - (int)blockIdx.x;   // heavy tiles first
    int tid  = threadIdx.x;
    int w    = tid >> 5;
    int lane = tid & 31;
    int gid  = lane >> 2;
    int tig  = lane & 3;

    int rbase = qt * 128 + w * 16;
    uint32_t* Pw = Ps + w * 16 * KS_STRIDE;

    // Q fragments (scale 1/8 folded in; exact power of 2)
    uint32_t aq[8][4];
    {
        const float* qp = Q + (size_t)rbase * C_EMB + hd * D_HEAD;
#pragma unroll
        for (int kk = 0; kk < 8; kk++) {
            aq[kk][0] = f2tf32(0.125f * qp[(size_t)gid * C_EMB + kk * 8 + tig]);
            aq[kk][1] = f2tf32(0.125f * qp[(size_t)(gid + 8) * C_EMB + kk * 8 + tig]);
            aq[kk][2] = f2tf32(0.125f * qp[(size_t)gid * C_EMB + kk * 8 + tig + 4]);
            aq[kk][3] = f2tf32(0.125f * qp[(size_t)(gid + 8) * C_EMB + kk * 8 + tig + 4]);
        }
    }

    float oacc[8][4];
#pragma unroll
    for (int i = 0; i < 8; i++)
#pragma unroll
        for (int r = 0; r < 4; r++) oacc[i][r] = 0.f;
    float m_lo = -1e30f, m_hi = -1e30f, l_lo = 0.f, l_hi = 0.f;

    int row0 = rbase + gid;
    int row1 = row0 + 8;
    int wrow_max = rbase + 15;

    int kb_last = 2 * qt + 1;
    for (int kb = 0; kb <= kb_last; kb++) {
        int kbase = kb * 64;
        // cooperative K/V tile load (64x64 each), convert to tf32
#pragma unroll
        for (int i = 0; i < 4; i++) {
            int id = tid + i * 256;
            int rr = id >> 4, c4 = (id & 15) * 4;
            size_t goff = (size_t)(kbase + rr) * C_EMB + hd * D_HEAD + c4;
            float4 kv = *(const float4*)(Kg + goff);
            float4 vv = *(const float4*)(Vg + goff);
            uint32_t* kd = Ks + rr * KS_STRIDE + c4;
            kd[0] = f2tf32(kv.x); kd[1] = f2tf32(kv.y);
            kd[2] = f2tf32(kv.z); kd[3] = f2tf32(kv.w);
            uint32_t* vd = Vs + rr * VS_STRIDE + c4;
            vd[0] = f2tf32(vv.x); vd[1] = f2tf32(vv.y);
            vd[2] = f2tf32(vv.z); vd[3] = f2tf32(vv.w);
        }
        __syncthreads();

        if (kbase <= wrow_max) {
            // S = Q K^T (scaled): 8 n-tiles (keys) x 8 k-steps (d)
            float sacc[8][4];
#pragma unroll
            for (int n = 0; n < 8; n++)
#pragma unroll
                for (int r = 0; r < 4; r++) sacc[n][r] = 0.f;
#pragma unroll
            for (int kk = 0; kk < 8; kk++) {
#pragma unroll
                for (int n = 0; n < 8; n++) {
                    uint32_t b[2];
                    const uint32_t* kp = Ks + (n * 8 + gid) * KS_STRIDE + kk * 8;
                    b[0] = kp[tig];
                    b[1] = kp[tig + 4];
                    mma_tf32(sacc[n], aq[kk], b);
                }
            }

            // causal mask + row max.
            // FIX: gate on the FIRST row of the warp (rbase), not the last.
            // A tile needs masking whenever it extends past ANY row it serves.
            bool boundary = (kbase + 63 > rbase);
            float ml0 = -1e30f, ml1 = -1e30f;
#pragma unroll
            for (int n = 0; n < 8; n++) {
                if (boundary) {
                    int c = kbase + n * 8 + 2 * tig;
                    if (c     > row0) sacc[n][0] = -1e30f;
                    if (c + 1 > row0) sacc[n][1] = -1e30f;
                    if (c     > row1) sacc[n][2] = -1e30f;
                    if (c + 1 > row1) sacc[n][3] = -1e30f;
                }
                ml0 = fmaxf(ml0, fmaxf(sacc[n][0], sacc[n][1]));
                ml1 = fmaxf(ml1, fmaxf(sacc[n][2], sacc[n][3]));
            }
            ml0 = fmaxf(ml0, __shfl_xor_sync(0xffffffffu, ml0, 1));
            ml0 = fmaxf(ml0, __shfl_xor_sync(0xffffffffu, ml0, 2));
            ml1 = fmaxf(ml1, __shfl_xor_sync(0xffffffffu, ml1, 1));
            ml1 = fmaxf(ml1, __shfl_xor_sync(0xffffffffu, ml1, 2));

            float mn0 = fmaxf(m_lo, ml0), mn1 = fmaxf(m_hi, ml1);
            float al0 = __expf(m_lo - mn0), al1 = __expf(m_hi - mn1);
            m_lo = mn0; m_hi = mn1;

            __syncwarp();   // prev-iter Ps reads complete before overwrite
            float ls0 = 0.f, ls1 = 0.f;
#pragma unroll
            for (int n = 0; n < 8; n++) {
                uint32_t q0 = f2tf32(__expf(sacc[n][0] - mn0));
                uint32_t q1 = f2tf32(__expf(sacc[n][1] - mn0));
                uint32_t q2 = f2tf32(__expf(sacc[n][2] - mn1));
                uint32_t q3 = f2tf32(__expf(sacc[n][3] - mn1));
                // sum the QUANTIZED p so normalization matches PV weights
                ls0 += __uint_as_float(q0) + __uint_as_float(q1);
                ls1 += __uint_as_float(q2) + __uint_as_float(q3);
                uint32_t* plo = Pw + gid * KS_STRIDE + n * 8 + 2 * tig;
                uint32_t* phi = Pw + (gid + 8) * KS_STRIDE + n * 8 + 2 * tig;
                plo[0] = q0; plo[1] = q1;
                phi[0] = q2; phi[1] = q3;
            }
            ls0 += __shfl_xor_sync(0xffffffffu, ls0, 1);
            ls0 += __shfl_xor_sync(0xffffffffu, ls0, 2);
            ls1 += __shfl_xor_sync(0xffffffffu, ls1, 1);
            ls1 += __shfl_xor_sync(0xffffffffu, ls1, 2);
            l_lo = l_lo * al0 + ls0;
            l_hi = l_hi * al1 + ls1;

            // rescale O
#pragma unroll
            for (int n = 0; n < 8; n++) {
                oacc[n][0] *= al0; oacc[n][1] *= al0;
                oacc[n][2] *= al1; oacc[n][3] *= al1;
            }
            __syncwarp();   // Ps writes visible to whole warp

            // O += P V : k-steps over keys, n-tiles over d
#pragma unroll
            for (int kt = 0; kt < 8; kt++) {
                uint32_t ap[4];
                const uint32_t* pp = Pw + gid * KS_STRIDE + kt * 8;
                const uint32_t* pq = Pw + (gid + 8) * KS_STRIDE + kt * 8;
                ap[0] = pp[tig];
                ap[1] = pq[tig];
                ap[2] = pp[tig + 4];
                ap[3] = pq[tig + 4];
#pragma unroll
                for (int n = 0; n < 8; n++) {
                    uint32_t b[2];
                    const uint32_t* vp = Vs + (kt * 8 + tig) * VS_STRIDE + n * 8 + gid;
                    b[0] = vp[0];
                    b[1] = vp[4 * VS_STRIDE];
                    mma_tf32(oacc[n], ap, b);
                }
            }
        }
        __syncthreads();
    }

    float inv0 = 1.0f / l_lo;
    float inv1 = 1.0f / l_hi;
    float* o0 = O + (size_t)row0 * C_EMB + hd * D_HEAD;
    float* o1 = O + (size_t)row1 * C_EMB + hd * D_HEAD;
#pragma unroll
    for (int n = 0; n < 8; n++) {
        int c = n * 8 + 2 * tig;
        float2 t0 = make_float2(oacc[n][0] * inv0, oacc[n][1] * inv0);
        float2 t1 = make_float2(oacc[n][2] * inv1, oacc[n][3] * inv1);
        *(float2*)(o0 + c) = t0;
        *(float2*)(o1 + c) = t1;
    }
}

// ----------------------------------------------------------------------------
// launch
// ----------------------------------------------------------------------------
extern "C" void kernel_launch(void* const* d_in, const int* in_sizes, int n_in,
                              void* d_out, int out_size)
{
    const float* x     = (const float*)d_in[0];
    const float* Wq    = (const float*)d_in[1];
    const float* bq    = (const float*)d_in[2];
    const float* Wk    = (const float*)d_in[3];
    const float* bk    = (const float*)d_in[4];
    const float* Wv    = (const float*)d_in[5];
    const float* bv    = (const float*)d_in[6];
    const float* Wo    = (const float*)d_in[7];
    const float* bo    = (const float*)d_in[8];
    const float* ln1_g = (const float*)d_in[9];
    const float* ln1_b = (const float*)d_in[10];
    const float* ln2_g = (const float*)d_in[11];
    const float* ln2_b = (const float*)d_in[12];
    const float* W1    = (const float*)d_in[13];
    const float* b1    = (const float*)d_in[14];
    const float* W2    = (const float*)d_in[15];
    const float* b2    = (const float*)d_in[16];
    float* out = (float*)d_out;

    float *h, *q, *k, *v, *ctx, *x2, *h2, *m1;
    cudaGetSymbolAddress((void**)&h,   g_h);
    cudaGetSymbolAddress((void**)&q,   g_q);
    cudaGetSymbolAddress((void**)&k,   g_k);
    cudaGetSymbolAddress((void**)&v,   g_v);
    cudaGetSymbolAddress((void**)&ctx, g_ctx);
    cudaGetSymbolAddress((void**)&x2,  g_x2);
    cudaGetSymbolAddress((void**)&h2,  g_h2);
    cudaGetSymbolAddress((void**)&m1,  g_m1);

    cudaFuncSetAttribute(fattn_k, cudaFuncAttributeMaxDynamicSharedMemorySize,
                         ATTN_SMEM_BYTES);

    dim3 gC(C_EMB / 128, T_SEQ / 128);
    dim3 gF(F_FFN / 128, T_SEQ / 128);

    layernorm_k<<<T_SEQ, 256>>>(x, ln1_g, ln1_b, h);
    mmgemm_k<0><<<gC, 256>>>(h, Wq, bq, nullptr, q, T_SEQ, C_EMB, C_EMB);
    mmgemm_k<0><<<gC, 256>>>(h, Wk, bk, nullptr, k, T_SEQ, C_EMB, C_EMB);
    mmgemm_k<0><<<gC, 256>>>(h, Wv, bv, nullptr, v, T_SEQ, C_EMB, C_EMB);
    fattn_k<<<dim3(T_SEQ / 128, N_HEAD), 256, ATTN_SMEM_BYTES>>>(q, k, v, ctx);
    mmgemm_k<0><<<gC, 256>>>(ctx, Wo, bo, h, x2, T_SEQ, C_EMB, C_EMB);
    layernorm_k<<<T_SEQ, 256>>>(x2, ln2_g, ln2_b, h2);
    mmgemm_k<1><<<gF, 256>>>(h2, W1, b1, nullptr, m1, T_SEQ, F_FFN, C_EMB);
    mmgemm_k<0><<<gC, 256>>>(m1, W2, b2, h2, out, T_SEQ, C_EMB, F_FFN);
}

// round 7
// speedup vs baseline: 3.8401x; 1.1447x over previous
#include <cuda_runtime.h>
#include <cuda_bf16.h>
#include <math.h>
#include <stdint.h>

// ----------------------------------------------------------------------------
// DecoderBlock: B=1, T=4096, C=768, H=12, D=64, F=3072
// Round 7: GEMM inner loop on ldmatrix (A row-major, B stored n-major; both
// fragments are the m8n8 pattern), fused QKV launch. Attention from R6.
// ----------------------------------------------------------------------------

#define T_SEQ 4096
#define C_EMB 768
#define N_HEAD 12
#define D_HEAD 64
#define F_FFN 3072

__device__ float g_h  [T_SEQ * C_EMB];
__device__ float g_q  [T_SEQ * C_EMB];
__device__ float g_k  [T_SEQ * C_EMB];
__device__ float g_v  [T_SEQ * C_EMB];
__device__ float g_ctx[T_SEQ * C_EMB];
__device__ float g_x2 [T_SEQ * C_EMB];
__device__ float g_h2 [T_SEQ * C_EMB];
__device__ float g_m1 [T_SEQ * F_FFN];

// ----------------------------------------------------------------------------
// LayerNorm (unchanged)
// ----------------------------------------------------------------------------
__global__ __launch_bounds__(256) void layernorm_k(
    const float* __restrict__ in, const float* __restrict__ gamma,
    const float* __restrict__ beta, float* __restrict__ out)
{
    int row = blockIdx.x;
    const float* xr = in + (size_t)row * C_EMB;
    float s = 0.f, s2 = 0.f;
    float v0[3];
#pragma unroll
    for (int i = 0; i < 3; i++) {
        float v = xr[threadIdx.x + i * 256];
        v0[i] = v;
        s += v; s2 += v * v;
    }
#pragma unroll
    for (int off = 16; off > 0; off >>= 1) {
        s  += __shfl_down_sync(0xffffffffu, s,  off);
        s2 += __shfl_down_sync(0xffffffffu, s2, off);
    }
    __shared__ float shs[8], shs2[8];
    int lane = threadIdx.x & 31, warp = threadIdx.x >> 5;
    if (lane == 0) { shs[warp] = s; shs2[warp] = s2; }
    __syncthreads();
    s = 0.f; s2 = 0.f;
#pragma unroll
    for (int i = 0; i < 8; i++) { s += shs[i]; s2 += shs2[i]; }
    float mu  = s * (1.0f / C_EMB);
    float var = s2 * (1.0f / C_EMB) - mu * mu;
    float inv = rsqrtf(var + 1e-5f);
    float* orow = out + (size_t)row * C_EMB;
#pragma unroll
    for (int i = 0; i < 3; i++) {
        int c = threadIdx.x + i * 256;
        orow[c] = (v0[i] - mu) * inv * gamma[c] + beta[c];
    }
}

// ----------------------------------------------------------------------------
// helpers
// ----------------------------------------------------------------------------
__device__ __forceinline__ uint32_t f2tf32(float f) {
    uint32_t r;
    asm("cvt.rna.tf32.f32 %0, %1;" : "=r"(r) : "f"(f));
    return r;
}

__device__ __forceinline__ void mma_tf32(float* d, const uint32_t* a, const uint32_t* b) {
    asm volatile(
        "mma.sync.aligned.m16n8k8.row.col.f32.tf32.tf32.f32 "
        "{%0,%1,%2,%3}, {%4,%5,%6,%7}, {%8,%9}, {%0,%1,%2,%3};\n"
        : "+f"(d[0]), "+f"(d[1]), "+f"(d[2]), "+f"(d[3])
        : "r"(a[0]), "r"(a[1]), "r"(a[2]), "r"(a[3]), "r"(b[0]), "r"(b[1]));
}

__device__ __forceinline__ uint32_t s2u(const void* p) {
    return (uint32_t)__cvta_generic_to_shared(p);
}

#define LDSM_X4(r0, r1, r2, r3, addr)                                          \
    asm volatile("ldmatrix.sync.aligned.m8n8.x4.shared.b16 {%0,%1,%2,%3}, [%4];" \
                 : "=r"(r0), "=r"(r1), "=r"(r2), "=r"(r3) : "r"(addr))

__device__ __forceinline__ float gelu_exact(float v) {
    return 0.5f * v * (1.0f + erff(v * 0.70710678118654752440f));
}

// ----------------------------------------------------------------------------
// tf32 GEMM body (ldmatrix fragments). BM=BN=128, BK=16, 256 thr, 8 warps 2x4.
// As[m][k] stride 20; Bs[n][k] stride 20 (n-major so fragments = A-pattern).
// ----------------------------------------------------------------------------
template<int ACT>
__device__ __forceinline__ void gemm_body(
    const float* __restrict__ A, const float* __restrict__ B,
    const float* __restrict__ bias, const float* __restrict__ res,
    float* __restrict__ C, int M, int N, int K, int bx, int by)
{
    constexpr int BK = 16;
    constexpr int S  = 20;                       // padded k-stride (words)
    __shared__ uint32_t As[2][128][S];
    __shared__ uint32_t Bs[2][128][S];

    int tid  = threadIdx.x;
    int lane = tid & 31;
    int wid  = tid >> 5;
    int wm   = wid & 1;
    int wn   = wid >> 1;
    int gid  = lane >> 2;
    int tig  = lane & 3;

    int bm = by * 128;
    int bn = bx * 128;

    // ldmatrix per-lane source rows/cols
    int a_row = wm * 64 + (lane & 15);           // + mt*16
    int a_col = (lane >> 4) << 2;                // 0 or 4 (+kk)
    int b_row = wn * 32 + ((lane >> 4) << 3) + (lane & 7);   // + np*16
    int b_col = ((lane >> 3) & 1) << 2;          // 0 or 4 (+kk)

    float acc[4][4][4];
#pragma unroll
    for (int i = 0; i < 4; i++)
#pragma unroll
        for (int j = 0; j < 4; j++)
#pragma unroll
            for (int r = 0; r < 4; r++) acc[i][j][r] = 0.f;

    int nt = K / BK;

    float4 av[2];
    float  bv[2][4];

    // ---- stage 0 fetch + store ----
#pragma unroll
    for (int i = 0; i < 2; i++) {
        int id = tid + i * 256;
        int r = id >> 2, c4 = id & 3;
        av[i] = *(const float4*)(A + (size_t)(bm + r) * K + c4 * 4);
        int n = id & 127, kg = id >> 7;
#pragma unroll
        for (int j = 0; j < 4; j++)
            bv[i][j] = B[(size_t)(kg * 4 + j) * N + bn + n];
    }
#pragma unroll
    for (int i = 0; i < 2; i++) {
        int id = tid + i * 256;
        int r = id >> 2, c4 = id & 3;
        uint4 ua = make_uint4(f2tf32(av[i].x), f2tf32(av[i].y),
                              f2tf32(av[i].z), f2tf32(av[i].w));
        *(uint4*)&As[0][r][c4 * 4] = ua;
        int n = id & 127, kg = id >> 7;
        uint4 ub = make_uint4(f2tf32(bv[i][0]), f2tf32(bv[i][1]),
                              f2tf32(bv[i][2]), f2tf32(bv[i][3]));
        *(uint4*)&Bs[0][n][kg * 4] = ub;
    }
    __syncthreads();

    for (int kt = 0; kt < nt; kt++) {
        int buf = kt & 1, nxt = buf ^ 1;
        bool has_next = (kt + 1 < nt);
        if (has_next) {
            int k0 = (kt + 1) * BK;
#pragma unroll
            for (int i = 0; i < 2; i++) {
                int id = tid + i * 256;
                int r = id >> 2, c4 = id & 3;
                av[i] = *(const float4*)(A + (size_t)(bm + r) * K + k0 + c4 * 4);
                int n = id & 127, kg = id >> 7;
#pragma unroll
                for (int j = 0; j < 4; j++)
                    bv[i][j] = B[(size_t)(k0 + kg * 4 + j) * N + bn + n];
            }
        }

#pragma unroll
        for (int ks = 0; ks < 2; ks++) {
            int kk = ks * 8;
            uint32_t af[4][4];
#pragma unroll
            for (int mt = 0; mt < 4; mt++) {
                uint32_t addr = s2u(&As[buf][a_row + mt * 16][kk + a_col]);
                LDSM_X4(af[mt][0], af[mt][1], af[mt][2], af[mt][3], addr);
            }
            uint32_t bf[4][2];
#pragma unroll
            for (int np = 0; np < 2; np++) {
                uint32_t addr = s2u(&Bs[buf][b_row + np * 16][kk + b_col]);
                LDSM_X4(bf[2 * np][0], bf[2 * np][1],
                        bf[2 * np + 1][0], bf[2 * np + 1][1], addr);
            }
#pragma unroll
            for (int mt = 0; mt < 4; mt++)
#pragma unroll
                for (int ntl = 0; ntl < 4; ntl++)
                    mma_tf32(acc[mt][ntl], af[mt], bf[ntl]);
        }

        if (has_next) {
#pragma unroll
            for (int i = 0; i < 2; i++) {
                int id = tid + i * 256;
                int r = id >> 2, c4 = id & 3;
                uint4 ua = make_uint4(f2tf32(av[i].x), f2tf32(av[i].y),
                                      f2tf32(av[i].z), f2tf32(av[i].w));
                *(uint4*)&As[nxt][r][c4 * 4] = ua;
                int n = id & 127, kg = id >> 7;
                uint4 ub = make_uint4(f2tf32(bv[i][0]), f2tf32(bv[i][1]),
                                      f2tf32(bv[i][2]), f2tf32(bv[i][3]));
                *(uint4*)&Bs[nxt][n][kg * 4] = ub;
            }
            __syncthreads();
        }
    }

    // epilogue (acc layout identical to R3)
#pragma unroll
    for (int mt = 0; mt < 4; mt++) {
#pragma unroll
        for (int ntl = 0; ntl < 4; ntl++) {
#pragma unroll
            for (int r = 0; r < 4; r++) {
                int row = bm + wm * 64 + mt * 16 + gid + (r >> 1) * 8;
                int col = bn + wn * 32 + ntl * 8 + tig * 2 + (r & 1);
                float v = acc[mt][ntl][r] + bias[col];
                if (res) v += res[(size_t)row * N + col];
                if (ACT == 1) v = gelu_exact(v);
                C[(size_t)row * N + col] = v;
            }
        }
    }
}

template<int ACT>
__global__ __launch_bounds__(256) void mmgemm_k(
    const float* __restrict__ A, const float* __restrict__ B,
    const float* __restrict__ bias, const float* __restrict__ res,
    float* __restrict__ C, int M, int N, int K)
{
    gemm_body<ACT>(A, B, bias, res, C, M, N, K, blockIdx.x, blockIdx.y);
}

// fused QKV: grid.x = 18; sel = x/6 picks {Wq,Wk,Wv}
__global__ __launch_bounds__(256) void mmgemm_qkv_k(
    const float* __restrict__ A,
    const float* __restrict__ B0, const float* __restrict__ b0, float* __restrict__ C0,
    const float* __restrict__ B1, const float* __restrict__ b1, float* __restrict__ C1,
    const float* __restrict__ B2, const float* __restrict__ b2, float* __restrict__ C2)
{
    int sel = blockIdx.x / 6;
    int bx  = blockIdx.x % 6;
    const float* B  = (sel == 0) ? B0 : (sel == 1) ? B1 : B2;
    const float* bb = (sel == 0) ? b0 : (sel == 1) ? b1 : b2;
    float*       C  = (sel == 0) ? C0 : (sel == 1) ? C1 : C2;
    gemm_body<0>(A, B, bb, nullptr, C, T_SEQ, C_EMB, C_EMB, bx, blockIdx.y);
}

// ----------------------------------------------------------------------------
// Flash attention (unchanged from R6, passing)
// ----------------------------------------------------------------------------
#define KS_STRIDE 68
#define VS_STRIDE 72
#define ATTN_SMEM_BYTES ((64 * KS_STRIDE + 64 * VS_STRIDE + 8 * 16 * KS_STRIDE) * 4)

__global__ __launch_bounds__(256, 2) void fattn_k(
    const float* __restrict__ Q, const float* __restrict__ Kg,
    const float* __restrict__ Vg, float* __restrict__ O)
{
    extern __shared__ uint32_t sm[];
    uint32_t* Ks = sm;
    uint32_t* Vs = Ks + 64 * KS_STRIDE;
    uint32_t* Ps = Vs + 64 * VS_STRIDE;

    int hd   = blockIdx.y;
    int qt   = (int)gridDim.x - 1 - (int)blockIdx.x;
    int tid  = threadIdx.x;
    int w    = tid >> 5;
    int lane = tid & 31;
    int gid  = lane >> 2;
    int tig  = lane & 3;

    int rbase = qt * 128 + w * 16;
    uint32_t* Pw = Ps + w * 16 * KS_STRIDE;

    uint32_t aq[8][4];
    {
        const float* qp = Q + (size_t)rbase * C_EMB + hd * D_HEAD;
#pragma unroll
        for (int kk = 0; kk < 8; kk++) {
            aq[kk][0] = f2tf32(0.125f * qp[(size_t)gid * C_EMB + kk * 8 + tig]);
            aq[kk][1] = f2tf32(0.125f * qp[(size_t)(gid + 8) * C_EMB + kk * 8 + tig]);
            aq[kk][2] = f2tf32(0.125f * qp[(size_t)gid * C_EMB + kk * 8 + tig + 4]);
            aq[kk][3] = f2tf32(0.125f * qp[(size_t)(gid + 8) * C_EMB + kk * 8 + tig + 4]);
        }
    }

    float oacc[8][4];
#pragma unroll
    for (int i = 0; i < 8; i++)
#pragma unroll
        for (int r = 0; r < 4; r++) oacc[i][r] = 0.f;
    float m_lo = -1e30f, m_hi = -1e30f, l_lo = 0.f, l_hi = 0.f;

    int row0 = rbase + gid;
    int row1 = row0 + 8;
    int wrow_max = rbase + 15;

    int kb_last = 2 * qt + 1;
    for (int kb = 0; kb <= kb_last; kb++) {
        int kbase = kb * 64;
#pragma unroll
        for (int i = 0; i < 4; i++) {
            int id = tid + i * 256;
            int rr = id >> 4, c4 = (id & 15) * 4;
            size_t goff = (size_t)(kbase + rr) * C_EMB + hd * D_HEAD + c4;
            float4 kv = *(const float4*)(Kg + goff);
            float4 vv = *(const float4*)(Vg + goff);
            uint32_t* kd = Ks + rr * KS_STRIDE + c4;
            kd[0] = f2tf32(kv.x); kd[1] = f2tf32(kv.y);
            kd[2] = f2tf32(kv.z); kd[3] = f2tf32(kv.w);
            uint32_t* vd = Vs + rr * VS_STRIDE + c4;
            vd[0] = f2tf32(vv.x); vd[1] = f2tf32(vv.y);
            vd[2] = f2tf32(vv.z); vd[3] = f2tf32(vv.w);
        }
        __syncthreads();

        if (kbase <= wrow_max) {
            float sacc[8][4];
#pragma unroll
            for (int n = 0; n < 8; n++)
#pragma unroll
                for (int r = 0; r < 4; r++) sacc[n][r] = 0.f;
#pragma unroll
            for (int kk = 0; kk < 8; kk++) {
#pragma unroll
                for (int n = 0; n < 8; n++) {
                    uint32_t b[2];
                    const uint32_t* kp = Ks + (n * 8 + gid) * KS_STRIDE + kk * 8;
                    b[0] = kp[tig];
                    b[1] = kp[tig + 4];
                    mma_tf32(sacc[n], aq[kk], b);
                }
            }

            bool boundary = (kbase + 63 > rbase);
            float ml0 = -1e30f, ml1 = -1e30f;
#pragma unroll
            for (int n = 0; n < 8; n++) {
                if (boundary) {
                    int c = kbase + n * 8 + 2 * tig;
                    if (c     > row0) sacc[n][0] = -1e30f;
                    if (c + 1 > row0) sacc[n][1] = -1e30f;
                    if (c     > row1) sacc[n][2] = -1e30f;
                    if (c + 1 > row1) sacc[n][3] = -1e30f;
                }
                ml0 = fmaxf(ml0, fmaxf(sacc[n][0], sacc[n][1]));
                ml1 = fmaxf(ml1, fmaxf(sacc[n][2], sacc[n][3]));
            }
            ml0 = fmaxf(ml0, __shfl_xor_sync(0xffffffffu, ml0, 1));
            ml0 = fmaxf(ml0, __shfl_xor_sync(0xffffffffu, ml0, 2));
            ml1 = fmaxf(ml1, __shfl_xor_sync(0xffffffffu, ml1, 1));
            ml1 = fmaxf(ml1, __shfl_xor_sync(0xffffffffu, ml1, 2));

            float mn0 = fmaxf(m_lo, ml0), mn1 = fmaxf(m_hi, ml1);
            float al0 = __expf(m_lo - mn0), al1 = __expf(m_hi - mn1);
            m_lo = mn0; m_hi = mn1;

            __syncwarp();
            float ls0 = 0.f, ls1 = 0.f;
#pragma unroll
            for (int n = 0; n < 8; n++) {
                uint32_t q0 = f2tf32(__expf(sacc[n][0] - mn0));
                uint32_t q1 = f2tf32(__expf(sacc[n][1] - mn0));
                uint32_t q2 = f2tf32(__expf(sacc[n][2] - mn1));
                uint32_t q3 = f2tf32(__expf(sacc[n][3] - mn1));
                ls0 += __uint_as_float(q0) + __uint_as_float(q1);
                ls1 += __uint_as_float(q2) + __uint_as_float(q3);
                uint32_t* plo = Pw + gid * KS_STRIDE + n * 8 + 2 * tig;
                uint32_t* phi = Pw + (gid + 8) * KS_STRIDE + n * 8 + 2 * tig;
                plo[0] = q0; plo[1] = q1;
                phi[0] = q2; phi[1] = q3;
            }
            ls0 += __shfl_xor_sync(0xffffffffu, ls0, 1);
            ls0 += __shfl_xor_sync(0xffffffffu, ls0, 2);
            ls1 += __shfl_xor_sync(0xffffffffu, ls1, 1);
            ls1 += __shfl_xor_sync(0xffffffffu, ls1, 2);
            l_lo = l_lo * al0 + ls0;
            l_hi = l_hi * al1 + ls1;

#pragma unroll
            for (int n = 0; n < 8; n++) {
                oacc[n][0] *= al0; oacc[n][1] *= al0;
                oacc[n][2] *= al1; oacc[n][3] *= al1;
            }
            __syncwarp();

#pragma unroll
            for (int kt = 0; kt < 8; kt++) {
                uint32_t ap[4];
                const uint32_t* pp = Pw + gid * KS_STRIDE + kt * 8;
                const uint32_t* pq = Pw + (gid + 8) * KS_STRIDE + kt * 8;
                ap[0] = pp[tig];
                ap[1] = pq[tig];
                ap[2] = pp[tig + 4];
                ap[3] = pq[tig + 4];
#pragma unroll
                for (int n = 0; n < 8; n++) {
                    uint32_t b[2];
                    const uint32_t* vp = Vs + (kt * 8 + tig) * VS_STRIDE + n * 8 + gid;
                    b[0] = vp[0];
                    b[1] = vp[4 * VS_STRIDE];
                    mma_tf32(oacc[n], ap, b);
                }
            }
        }
        __syncthreads();
    }

    float inv0 = 1.0f / l_lo;
    float inv1 = 1.0f / l_hi;
    float* o0 = O + (size_t)row0 * C_EMB + hd * D_HEAD;
    float* o1 = O + (size_t)row1 * C_EMB + hd * D_HEAD;
#pragma unroll
    for (int n = 0; n < 8; n++) {
        int c = n * 8 + 2 * tig;
        float2 t0 = make_float2(oacc[n][0] * inv0, oacc[n][1] * inv0);
        float2 t1 = make_float2(oacc[n][2] * inv1, oacc[n][3] * inv1);
        *(float2*)(o0 + c) = t0;
        *(float2*)(o1 + c) = t1;
    }
}

// ----------------------------------------------------------------------------
// launch
// ----------------------------------------------------------------------------
extern "C" void kernel_launch(void* const* d_in, const int* in_sizes, int n_in,
                              void* d_out, int out_size)
{
    const float* x     = (const float*)d_in[0];
    const float* Wq    = (const float*)d_in[1];
    const float* bq    = (const float*)d_in[2];
    const float* Wk    = (const float*)d_in[3];
    const float* bk    = (const float*)d_in[4];
    const float* Wv    = (const float*)d_in[5];
    const float* bv    = (const float*)d_in[6];
    const float* Wo    = (const float*)d_in[7];
    const float* bo    = (const float*)d_in[8];
    const float* ln1_g = (const float*)d_in[9];
    const float* ln1_b = (const float*)d_in[10];
    const float* ln2_g = (const float*)d_in[11];
    const float* ln2_b = (const float*)d_in[12];
    const float* W1    = (const float*)d_in[13];
    const float* b1    = (const float*)d_in[14];
    const float* W2    = (const float*)d_in[15];
    const float* b2    = (const float*)d_in[16];
    float* out = (float*)d_out;

    float *h, *q, *k, *v, *ctx, *x2, *h2, *m1;
    cudaGetSymbolAddress((void**)&h,   g_h);
    cudaGetSymbolAddress((void**)&q,   g_q);
    cudaGetSymbolAddress((void**)&k,   g_k);
    cudaGetSymbolAddress((void**)&v,   g_v);
    cudaGetSymbolAddress((void**)&ctx, g_ctx);
    cudaGetSymbolAddress((void**)&x2,  g_x2);
    cudaGetSymbolAddress((void**)&h2,  g_h2);
    cudaGetSymbolAddress((void**)&m1,  g_m1);

    cudaFuncSetAttribute(fattn_k, cudaFuncAttributeMaxDynamicSharedMemorySize,
                         ATTN_SMEM_BYTES);

    dim3 gC(C_EMB / 128, T_SEQ / 128);     // (6, 32)
    dim3 gQKV(18, T_SEQ / 128);            // fused q,k,v
    dim3 gF(F_FFN / 128, T_SEQ / 128);     // (24, 32)

    layernorm_k<<<T_SEQ, 256>>>(x, ln1_g, ln1_b, h);
    mmgemm_qkv_k<<<gQKV, 256>>>(h, Wq, bq, q, Wk, bk, k, Wv, bv, v);
    fattn_k<<<dim3(T_SEQ / 128, N_HEAD), 256, ATTN_SMEM_BYTES>>>(q, k, v, ctx);
    mmgemm_k<0><<<gC, 256>>>(ctx, Wo, bo, h, x2, T_SEQ, C_EMB, C_EMB);
    layernorm_k<<<T_SEQ, 256>>>(x2, ln2_g, ln2_b, h2);
    mmgemm_k<1><<<gF, 256>>>(h2, W1, b1, nullptr, m1, T_SEQ, F_FFN, C_EMB);
    mmgemm_k<0><<<gC, 256>>>(m1, W2, b2, h2, out, T_SEQ, C_EMB, F_FFN);
}

// round 8
// speedup vs baseline: 4.1520x; 1.0812x over previous
#include <cuda_runtime.h>
#include <cuda_bf16.h>
#include <math.h>
#include <stdint.h>

// ----------------------------------------------------------------------------
// DecoderBlock: B=1, T=4096, C=768, H=12, D=64, F=3072
// Round 8: issue-slot reduction. Raw-f32-as-tf32 (truncation; mma ignores low
// 13 mantissa bits) removes all cvt from hot loops; attention S-phase K frags
// and PV-phase P frags via ldmatrix; P stored with STS.64. QKV stays fused.
// ----------------------------------------------------------------------------

#define T_SEQ 4096
#define C_EMB 768
#define N_HEAD 12
#define D_HEAD 64
#define F_FFN 3072

__device__ float g_h  [T_SEQ * C_EMB];
__device__ float g_q  [T_SEQ * C_EMB];
__device__ float g_k  [T_SEQ * C_EMB];
__device__ float g_v  [T_SEQ * C_EMB];
__device__ float g_ctx[T_SEQ * C_EMB];
__device__ float g_x2 [T_SEQ * C_EMB];
__device__ float g_h2 [T_SEQ * C_EMB];
__device__ float g_m1 [T_SEQ * F_FFN];

// ----------------------------------------------------------------------------
// LayerNorm (unchanged)
// ----------------------------------------------------------------------------
__global__ __launch_bounds__(256) void layernorm_k(
    const float* __restrict__ in, const float* __restrict__ gamma,
    const float* __restrict__ beta, float* __restrict__ out)
{
    int row = blockIdx.x;
    const float* xr = in + (size_t)row * C_EMB;
    float s = 0.f, s2 = 0.f;
    float v0[3];
#pragma unroll
    for (int i = 0; i < 3; i++) {
        float v = xr[threadIdx.x + i * 256];
        v0[i] = v;
        s += v; s2 += v * v;
    }
#pragma unroll
    for (int off = 16; off > 0; off >>= 1) {
        s  += __shfl_down_sync(0xffffffffu, s,  off);
        s2 += __shfl_down_sync(0xffffffffu, s2, off);
    }
    __shared__ float shs[8], shs2[8];
    int lane = threadIdx.x & 31, warp = threadIdx.x >> 5;
    if (lane == 0) { shs[warp] = s; shs2[warp] = s2; }
    __syncthreads();
    s = 0.f; s2 = 0.f;
#pragma unroll
    for (int i = 0; i < 8; i++) { s += shs[i]; s2 += shs2[i]; }
    float mu  = s * (1.0f / C_EMB);
    float var = s2 * (1.0f / C_EMB) - mu * mu;
    float inv = rsqrtf(var + 1e-5f);
    float* orow = out + (size_t)row * C_EMB;
#pragma unroll
    for (int i = 0; i < 3; i++) {
        int c = threadIdx.x + i * 256;
        orow[c] = (v0[i] - mu) * inv * gamma[c] + beta[c];
    }
}

// ----------------------------------------------------------------------------
// helpers
// ----------------------------------------------------------------------------
__device__ __forceinline__ void mma_tf32(float* d, const uint32_t* a, const uint32_t* b) {
    asm volatile(
        "mma.sync.aligned.m16n8k8.row.col.f32.tf32.tf32.f32 "
        "{%0,%1,%2,%3}, {%4,%5,%6,%7}, {%8,%9}, {%0,%1,%2,%3};\n"
        : "+f"(d[0]), "+f"(d[1]), "+f"(d[2]), "+f"(d[3])
        : "r"(a[0]), "r"(a[1]), "r"(a[2]), "r"(a[3]), "r"(b[0]), "r"(b[1]));
}

__device__ __forceinline__ uint32_t s2u(const void* p) {
    return (uint32_t)__cvta_generic_to_shared(p);
}

#define LDSM_X4(r0, r1, r2, r3, addr)                                          \
    asm volatile("ldmatrix.sync.aligned.m8n8.x4.shared.b16 {%0,%1,%2,%3}, [%4];" \
                 : "=r"(r0), "=r"(r1), "=r"(r2), "=r"(r3) : "r"(addr))

__device__ __forceinline__ float gelu_exact(float v) {
    return 0.5f * v * (1.0f + erff(v * 0.70710678118654752440f));
}

// ----------------------------------------------------------------------------
// tf32 GEMM body (ldmatrix fragments, raw f32 bits as tf32 operands).
// BM=BN=128, BK=16, 256 thr, 8 warps 2x4. As[m][k], Bs[n][k], stride 20.
// ----------------------------------------------------------------------------
template<int ACT>
__device__ __forceinline__ void gemm_body(
    const float* __restrict__ A, const float* __restrict__ B,
    const float* __restrict__ bias, const float* __restrict__ res,
    float* __restrict__ C, int M, int N, int K, int bx, int by)
{
    constexpr int BK = 16;
    constexpr int S  = 20;
    __shared__ uint32_t As[2][128][S];
    __shared__ uint32_t Bs[2][128][S];

    int tid  = threadIdx.x;
    int lane = tid & 31;
    int wid  = tid >> 5;
    int wm   = wid & 1;
    int wn   = wid >> 1;
    int gid  = lane >> 2;
    int tig  = lane & 3;

    int bm = by * 128;
    int bn = bx * 128;

    int a_row = wm * 64 + (lane & 15);
    int a_col = (lane >> 4) << 2;
    int b_row = wn * 32 + ((lane >> 4) << 3) + (lane & 7);
    int b_col = ((lane >> 3) & 1) << 2;

    float acc[4][4][4];
#pragma unroll
    for (int i = 0; i < 4; i++)
#pragma unroll
        for (int j = 0; j < 4; j++)
#pragma unroll
            for (int r = 0; r < 4; r++) acc[i][j][r] = 0.f;

    int nt = K / BK;

    uint4 av[2];
    uint32_t bv[2][4];

#pragma unroll
    for (int i = 0; i < 2; i++) {
        int id = tid + i * 256;
        int r = id >> 2, c4 = id & 3;
        av[i] = *(const uint4*)(A + (size_t)(bm + r) * K + c4 * 4);
        int n = id & 127, kg = id >> 7;
#pragma unroll
        for (int j = 0; j < 4; j++)
            bv[i][j] = __float_as_uint(B[(size_t)(kg * 4 + j) * N + bn + n]);
    }
#pragma unroll
    for (int i = 0; i < 2; i++) {
        int id = tid + i * 256;
        int r = id >> 2, c4 = id & 3;
        *(uint4*)&As[0][r][c4 * 4] = av[i];
        int n = id & 127, kg = id >> 7;
        *(uint4*)&Bs[0][n][kg * 4] = make_uint4(bv[i][0], bv[i][1], bv[i][2], bv[i][3]);
    }
    __syncthreads();

    for (int kt = 0; kt < nt; kt++) {
        int buf = kt & 1, nxt = buf ^ 1;
        bool has_next = (kt + 1 < nt);
        if (has_next) {
            int k0 = (kt + 1) * BK;
#pragma unroll
            for (int i = 0; i < 2; i++) {
                int id = tid + i * 256;
                int r = id >> 2, c4 = id & 3;
                av[i] = *(const uint4*)(A + (size_t)(bm + r) * K + k0 + c4 * 4);
                int n = id & 127, kg = id >> 7;
#pragma unroll
                for (int j = 0; j < 4; j++)
                    bv[i][j] = __float_as_uint(B[(size_t)(k0 + kg * 4 + j) * N + bn + n]);
            }
        }

#pragma unroll
        for (int ks = 0; ks < 2; ks++) {
            int kk = ks * 8;
            uint32_t af[4][4];
#pragma unroll
            for (int mt = 0; mt < 4; mt++) {
                uint32_t addr = s2u(&As[buf][a_row + mt * 16][kk + a_col]);
                LDSM_X4(af[mt][0], af[mt][1], af[mt][2], af[mt][3], addr);
            }
            uint32_t bf[4][2];
#pragma unroll
            for (int np = 0; np < 2; np++) {
                uint32_t addr = s2u(&Bs[buf][b_row + np * 16][kk + b_col]);
                LDSM_X4(bf[2 * np][0], bf[2 * np][1],
                        bf[2 * np + 1][0], bf[2 * np + 1][1], addr);
            }
#pragma unroll
            for (int mt = 0; mt < 4; mt++)
#pragma unroll
                for (int ntl = 0; ntl < 4; ntl++)
                    mma_tf32(acc[mt][ntl], af[mt], bf[ntl]);
        }

        if (has_next) {
#pragma unroll
            for (int i = 0; i < 2; i++) {
                int id = tid + i * 256;
                int r = id >> 2, c4 = id & 3;
                *(uint4*)&As[nxt][r][c4 * 4] = av[i];
                int n = id & 127, kg = id >> 7;
                *(uint4*)&Bs[nxt][n][kg * 4] = make_uint4(bv[i][0], bv[i][1], bv[i][2], bv[i][3]);
            }
            __syncthreads();
        }
    }

#pragma unroll
    for (int mt = 0; mt < 4; mt++) {
#pragma unroll
        for (int ntl = 0; ntl < 4; ntl++) {
#pragma unroll
            for (int r = 0; r < 4; r++) {
                int row = bm + wm * 64 + mt * 16 + gid + (r >> 1) * 8;
                int col = bn + wn * 32 + ntl * 8 + tig * 2 + (r & 1);
                float v = acc[mt][ntl][r] + bias[col];
                if (res) v += res[(size_t)row * N + col];
                if (ACT == 1) v = gelu_exact(v);
                C[(size_t)row * N + col] = v;
            }
        }
    }
}

template<int ACT>
__global__ __launch_bounds__(256) void mmgemm_k(
    const float* __restrict__ A, const float* __restrict__ B,
    const float* __restrict__ bias, const float* __restrict__ res,
    float* __restrict__ C, int M, int N, int K)
{
    gemm_body<ACT>(A, B, bias, res, C, M, N, K, blockIdx.x, blockIdx.y);
}

__global__ __launch_bounds__(256) void mmgemm_qkv_k(
    const float* __restrict__ A,
    const float* __restrict__ B0, const float* __restrict__ b0, float* __restrict__ C0,
    const float* __restrict__ B1, const float* __restrict__ b1, float* __restrict__ C1,
    const float* __restrict__ B2, const float* __restrict__ b2, float* __restrict__ C2)
{
    int sel = blockIdx.x / 6;
    int bx  = blockIdx.x % 6;
    const float* B  = (sel == 0) ? B0 : (sel == 1) ? B1 : B2;
    const float* bb = (sel == 0) ? b0 : (sel == 1) ? b1 : b2;
    float*       C  = (sel == 0) ? C0 : (sel == 1) ? C1 : C2;
    gemm_body<0>(A, B, bb, nullptr, C, T_SEQ, C_EMB, C_EMB, bx, blockIdx.y);
}

// ----------------------------------------------------------------------------
// Flash attention: ldmatrix for K b-frags (S phase) + P a-frags (PV phase),
// raw f32 bits as tf32 operands, STS.64 P stores. Fixed causal gate.
// ----------------------------------------------------------------------------
#define KS_STRIDE 68
#define VS_STRIDE 72
#define ATTN_SMEM_BYTES ((64 * KS_STRIDE + 64 * VS_STRIDE + 8 * 16 * KS_STRIDE) * 4)

__global__ __launch_bounds__(256, 2) void fattn_k(
    const float* __restrict__ Q, const float* __restrict__ Kg,
    const float* __restrict__ Vg, float* __restrict__ O)
{
    extern __shared__ uint32_t sm[];
    uint32_t* Ks = sm;                         // [64][68]
    uint32_t* Vs = Ks + 64 * KS_STRIDE;        // [64][72]
    uint32_t* Ps = Vs + 64 * VS_STRIDE;        // [8][16][68]

    int hd   = blockIdx.y;
    int qt   = (int)gridDim.x - 1 - (int)blockIdx.x;
    int tid  = threadIdx.x;
    int w    = tid >> 5;
    int lane = tid & 31;
    int gid  = lane >> 2;
    int tig  = lane & 3;

    int rbase = qt * 128 + w * 16;
    uint32_t* Pw = Ps + w * 16 * KS_STRIDE;

    // ldmatrix lane patterns
    int bs_row = ((lane >> 4) << 3) + (lane & 7);    // K b-frag: + np*16
    int bs_col = ((lane >> 3) & 1) << 2;
    int pa_row = lane & 15;                          // P a-frag
    int pa_col = (lane >> 4) << 2;

    // Q fragments (scale 1/8, raw bits)
    uint32_t aq[8][4];
    {
        const float* qp = Q + (size_t)rbase * C_EMB + hd * D_HEAD;
#pragma unroll
        for (int kk = 0; kk < 8; kk++) {
            aq[kk][0] = __float_as_uint(0.125f * qp[(size_t)gid * C_EMB + kk * 8 + tig]);
            aq[kk][1] = __float_as_uint(0.125f * qp[(size_t)(gid + 8) * C_EMB + kk * 8 + tig]);
            aq[kk][2] = __float_as_uint(0.125f * qp[(size_t)gid * C_EMB + kk * 8 + tig + 4]);
            aq[kk][3] = __float_as_uint(0.125f * qp[(size_t)(gid + 8) * C_EMB + kk * 8 + tig + 4]);
        }
    }

    float oacc[8][4];
#pragma unroll
    for (int i = 0; i < 8; i++)
#pragma unroll
        for (int r = 0; r < 4; r++) oacc[i][r] = 0.f;
    float m_lo = -1e30f, m_hi = -1e30f, l_lo = 0.f, l_hi = 0.f;

    int row0 = rbase + gid;
    int row1 = row0 + 8;
    int wrow_max = rbase + 15;

    int kb_last = 2 * qt + 1;
    for (int kb = 0; kb <= kb_last; kb++) {
        int kbase = kb * 64;
        // cooperative K/V tile load (raw f32 bits, vectorized)
#pragma unroll
        for (int i = 0; i < 4; i++) {
            int id = tid + i * 256;
            int rr = id >> 4, c4 = (id & 15) * 4;
            size_t goff = (size_t)(kbase + rr) * C_EMB + hd * D_HEAD + c4;
            uint4 kv = *(const uint4*)(Kg + goff);
            uint4 vv = *(const uint4*)(Vg + goff);
            *(uint4*)(Ks + rr * KS_STRIDE + c4) = kv;
            *(uint4*)(Vs + rr * VS_STRIDE + c4) = vv;
        }
        __syncthreads();

        if (kbase <= wrow_max) {
            // S = Q K^T : b-frags via ldmatrix (n-major Ks)
            float sacc[8][4];
#pragma unroll
            for (int n = 0; n < 8; n++)
#pragma unroll
                for (int r = 0; r < 4; r++) sacc[n][r] = 0.f;
#pragma unroll
            for (int kk = 0; kk < 8; kk++) {
#pragma unroll
                for (int np = 0; np < 4; np++) {
                    uint32_t b4[4];
                    uint32_t addr = s2u(&Ks[(bs_row + np * 16) * KS_STRIDE + kk * 8 + bs_col]);
                    LDSM_X4(b4[0], b4[1], b4[2], b4[3], addr);
                    mma_tf32(sacc[2 * np],     aq[kk], b4);
                    mma_tf32(sacc[2 * np + 1], aq[kk], b4 + 2);
                }
            }

            // causal mask (gate on FIRST row of warp) + row max
            bool boundary = (kbase + 63 > rbase);
            float ml0 = -1e30f, ml1 = -1e30f;
#pragma unroll
            for (int n = 0; n < 8; n++) {
                if (boundary) {
                    int c = kbase + n * 8 + 2 * tig;
                    if (c     > row0) sacc[n][0] = -1e30f;
                    if (c + 1 > row0) sacc[n][1] = -1e30f;
                    if (c     > row1) sacc[n][2] = -1e30f;
                    if (c + 1 > row1) sacc[n][3] = -1e30f;
                }
                ml0 = fmaxf(ml0, fmaxf(sacc[n][0], sacc[n][1]));
                ml1 = fmaxf(ml1, fmaxf(sacc[n][2], sacc[n][3]));
            }
            ml0 = fmaxf(ml0, __shfl_xor_sync(0xffffffffu, ml0, 1));
            ml0 = fmaxf(ml0, __shfl_xor_sync(0xffffffffu, ml0, 2));
            ml1 = fmaxf(ml1, __shfl_xor_sync(0xffffffffu, ml1, 1));
            ml1 = fmaxf(ml1, __shfl_xor_sync(0xffffffffu, ml1, 2));

            float mn0 = fmaxf(m_lo, ml0), mn1 = fmaxf(m_hi, ml1);
            float al0 = __expf(m_lo - mn0), al1 = __expf(m_hi - mn1);
            m_lo = mn0; m_hi = mn1;

            __syncwarp();   // prev-iter Ps reads complete before overwrite
            float ls0 = 0.f, ls1 = 0.f;
#pragma unroll
            for (int n = 0; n < 8; n++) {
                float p0 = __expf(sacc[n][0] - mn0);
                float p1 = __expf(sacc[n][1] - mn0);
                float p2 = __expf(sacc[n][2] - mn1);
                float p3 = __expf(sacc[n][3] - mn1);
                ls0 += p0 + p1;
                ls1 += p2 + p3;
                *(uint2*)(Pw + gid * KS_STRIDE + n * 8 + 2 * tig) =
                    make_uint2(__float_as_uint(p0), __float_as_uint(p1));
                *(uint2*)(Pw + (gid + 8) * KS_STRIDE + n * 8 + 2 * tig) =
                    make_uint2(__float_as_uint(p2), __float_as_uint(p3));
            }
            ls0 += __shfl_xor_sync(0xffffffffu, ls0, 1);
            ls0 += __shfl_xor_sync(0xffffffffu, ls0, 2);
            ls1 += __shfl_xor_sync(0xffffffffu, ls1, 1);
            ls1 += __shfl_xor_sync(0xffffffffu, ls1, 2);
            l_lo = l_lo * al0 + ls0;
            l_hi = l_hi * al1 + ls1;

#pragma unroll
            for (int n = 0; n < 8; n++) {
                oacc[n][0] *= al0; oacc[n][1] *= al0;
                oacc[n][2] *= al1; oacc[n][3] *= al1;
            }
            __syncwarp();   // Ps writes visible to whole warp

            // O += P V : P a-frags via ldmatrix; V b-frags scalar (conflict-free)
#pragma unroll
            for (int kt = 0; kt < 8; kt++) {
                uint32_t ap[4];
                uint32_t addr = s2u(&Pw[pa_row * KS_STRIDE + kt * 8 + pa_col]);
                LDSM_X4(ap[0], ap[1], ap[2], ap[3], addr);
#pragma unroll
                for (int n = 0; n < 8; n++) {
                    uint32_t b[2];
                    const uint32_t* vp = Vs + (kt * 8 + tig) * VS_STRIDE + n * 8 + gid;
                    b[0] = vp[0];
                    b[1] = vp[4 * VS_STRIDE];
                    mma_tf32(oacc[n], ap, b);
                }
            }
        }
        __syncthreads();
    }

    float inv0 = 1.0f / l_lo;
    float inv1 = 1.0f / l_hi;
    float* o0 = O + (size_t)row0 * C_EMB + hd * D_HEAD;
    float* o1 = O + (size_t)row1 * C_EMB + hd * D_HEAD;
#pragma unroll
    for (int n = 0; n < 8; n++) {
        int c = n * 8 + 2 * tig;
        float2 t0 = make_float2(oacc[n][0] * inv0, oacc[n][1] * inv0);
        float2 t1 = make_float2(oacc[n][2] * inv1, oacc[n][3] * inv1);
        *(float2*)(o0 + c) = t0;
        *(float2*)(o1 + c) = t1;
    }
}

// ----------------------------------------------------------------------------
// launch
// ----------------------------------------------------------------------------
extern "C" void kernel_launch(void* const* d_in, const int* in_sizes, int n_in,
                              void* d_out, int out_size)
{
    const float* x     = (const float*)d_in[0];
    const float* Wq    = (const float*)d_in[1];
    const float* bq    = (const float*)d_in[2];
    const float* Wk    = (const float*)d_in[3];
    const float* bk    = (const float*)d_in[4];
    const float* Wv    = (const float*)d_in[5];
    const float* bv    = (const float*)d_in[6];
    const float* Wo    = (const float*)d_in[7];
    const float* bo    = (const float*)d_in[8];
    const float* ln1_g = (const float*)d_in[9];
    const float* ln1_b = (const float*)d_in[10];
    const float* ln2_g = (const float*)d_in[11];
    const float* ln2_b = (const float*)d_in[12];
    const float* W1    = (const float*)d_in[13];
    const float* b1    = (const float*)d_in[14];
    const float* W2    = (const float*)d_in[15];
    const float* b2    = (const float*)d_in[16];
    float* out = (float*)d_out;

    float *h, *q, *k, *v, *ctx, *x2, *h2, *m1;
    cudaGetSymbolAddress((void**)&h,   g_h);
    cudaGetSymbolAddress((void**)&q,   g_q);
    cudaGetSymbolAddress((void**)&k,   g_k);
    cudaGetSymbolAddress((void**)&v,   g_v);
    cudaGetSymbolAddress((void**)&ctx, g_ctx);
    cudaGetSymbolAddress((void**)&x2,  g_x2);
    cudaGetSymbolAddress((void**)&h2,  g_h2);
    cudaGetSymbolAddress((void**)&m1,  g_m1);

    cudaFuncSetAttribute(fattn_k, cudaFuncAttributeMaxDynamicSharedMemorySize,
                         ATTN_SMEM_BYTES);

    dim3 gC(C_EMB / 128, T_SEQ / 128);     // (6, 32)
    dim3 gQKV(18, T_SEQ / 128);
    dim3 gF(F_FFN / 128, T_SEQ / 128);     // (24, 32)

    layernorm_k<<<T_SEQ, 256>>>(x, ln1_g, ln1_b, h);
    mmgemm_qkv_k<<<gQKV, 256>>>(h, Wq, bq, q, Wk, bk, k, Wv, bv, v);
    fattn_k<<<dim3(T_SEQ / 128, N_HEAD), 256, ATTN_SMEM_BYTES>>>(q, k, v, ctx);
    mmgemm_k<0><<<gC, 256>>>(ctx, Wo, bo, h, x2, T_SEQ, C_EMB, C_EMB);
    layernorm_k<<<T_SEQ, 256>>>(x2, ln2_g, ln2_b, h2);
    mmgemm_k<1><<<gF, 256>>>(h2, W1, b1, nullptr, m1, T_SEQ, F_FFN, C_EMB);
    mmgemm_k<0><<<gC, 256>>>(m1, W2, b2, h2, out, T_SEQ, C_EMB, F_FFN);
}